// round 11
// baseline (speedup 1.0000x reference)
#include <cuda_runtime.h>
#include <cstdint>

#define TT   1024
#define BB   64
#define DIN  400
#define HH   128
#define G4   512
#define HD1  256
#define HD2  64
#define NROW (TT*BB)

// ---------------- scratch (device globals; no runtime allocation) ----------------
__device__ float g_G  [(size_t)2*NROW*G4];   // gate preactivations, both dirs
__device__ float g_X1 [(size_t)NROW*HD1];    // layer0 output [t][b][256]
__device__ float g_X2 [(size_t)NROW*HD1];    // layer1 output [t][b][256]
__device__ float g_HL [(size_t)NROW*2];      // precomputed h-part of logits
__device__ float g_Wp [HD2*HD1];             // BN1-folded linear weight
__device__ float g_bp [HD2];                 // BN1-folded linear bias
__device__ float g_Wh2[2*HD2];               // BN2-folded output weight (h part)
__device__ float g_hb [2];                   // BN2-folded output bias

// ---------------- prep: fold BN1/BN2 into linear / output weights ----------------
__global__ void k_prep(const float* bn1g, const float* bn1b, const float* bn1m, const float* bn1v,
                       const float* linw, const float* linb,
                       const float* bn2g, const float* bn2b, const float* bn2m, const float* bn2v,
                       const float* outw, const float* outb) {
    __shared__ float s1[HD1], t1[HD1], s2[HD2], t2[HD2];
    int tid = threadIdx.x;
    if (tid < HD1) { float s = bn1g[tid]*rsqrtf(bn1v[tid]+1e-5f); s1[tid]=s; t1[tid]=bn1b[tid]-bn1m[tid]*s; }
    if (tid < HD2) { float s = bn2g[tid]*rsqrtf(bn2v[tid]+1e-5f); s2[tid]=s; t2[tid]=bn2b[tid]-bn2m[tid]*s; }
    __syncthreads();
    for (int i = tid; i < HD2*HD1; i += blockDim.x) g_Wp[i] = linw[i]*s1[i & (HD1-1)];
    if (tid < HD2) {
        float a = linb[tid];
        for (int j = 0; j < HD1; j++) a += t1[j]*linw[tid*HD1+j];
        g_bp[tid] = a;
    }
    if (tid < 2*HD2) { int k = tid>>6, c = tid&63; g_Wh2[tid] = outw[k*68+4+c]*s2[c]; }
    if (tid < 2) {
        float a = outb[tid];
        for (int c = 0; c < HD2; c++) a += t2[c]*outw[tid*68+4+c];
        g_hb[tid] = a;
    }
}

// ---------------- mma helpers (raw f32 bits fed as tf32: HW truncates) ----------------
__device__ __forceinline__ void mma_tf32(float* c, unsigned a0, unsigned a1, unsigned a2, unsigned a3,
                                         unsigned b0, unsigned b1) {
    asm volatile("mma.sync.aligned.m16n8k8.row.col.f32.tf32.tf32.f32 "
                 "{%0,%1,%2,%3}, {%4,%5,%6,%7}, {%8,%9}, {%0,%1,%2,%3};"
                 : "+f"(c[0]), "+f"(c[1]), "+f"(c[2]), "+f"(c[3])
                 : "r"(a0), "r"(a1), "r"(a2), "r"(a3), "r"(b0), "r"(b1));
}
__device__ __forceinline__ void cpa16(unsigned dst, const float* src) {
    asm volatile("cp.async.ca.shared.global [%0], [%1], 16;" :: "r"(dst), "l"(src) : "memory");
}

// ---------------- f32x2 packed helpers ----------------
__device__ __forceinline__ unsigned long long ff2(unsigned long long a, unsigned long long b,
                                                  unsigned long long c) {
    unsigned long long d;
    asm("fma.rn.f32x2 %0, %1, %2, %3;" : "=l"(d) : "l"(a), "l"(b), "l"(c));
    return d;
}
__device__ __forceinline__ float hsum2(unsigned long long a) {
    float x, y;
    asm("mov.b64 {%0,%1}, %2;" : "=f"(x), "=f"(y) : "l"(a));
    return x + y;
}

// ---------------- input-projection GEMM (tensor cores, tf32, cp.async) ----------------
#define APAD 20
#define BPAD 136
__global__ void __launch_bounds__(256) k_gemm(
    const float* __restrict__ x,
    const float* __restrict__ Wf, const float* __restrict__ bif, const float* __restrict__ bhf,
    const float* __restrict__ Wr, const float* __restrict__ bir, const float* __restrict__ bhr,
    int Kdim, int layer)
{
    __shared__ __align__(16) unsigned As[2][128][APAD];
    __shared__ __align__(16) unsigned Bs[2][16][BPAD];

    int tid  = threadIdx.x;
    int row0 = blockIdx.x*128, col0 = blockIdx.y*128;
    int dir  = blockIdx.z;
    const float* W  = dir ? Wr  : Wf;
    const float* bi = dir ? bir : bif;
    const float* bh = dir ? bhr : bhf;

    unsigned asb = (unsigned)__cvta_generic_to_shared(&As[0][0][0]);
    const unsigned ASTAGE = 128*APAD*4;

    const float* pA[2]; unsigned sAb[2];
    const float* pB[2]; int sB[2];
#pragma unroll
    for (int i = 0; i < 2; i++) {
        int t = tid + i*256;
        int rA = t >> 2, qA = t & 3;
        int r = row0 + rA;
        if (layer == 0) { int tt = r >> 6, b = r & 63; pA[i] = x + ((size_t)b*TT + tt)*DIN + qA*4; }
        else            { pA[i] = g_X1 + (size_t)r*HD1 + qA*4; }
        sAb[i] = (unsigned)(rA*APAD + qA*4)*4;
        int qB = t >> 7, colB = t & 127;
        pB[i] = W + (size_t)(col0 + colB)*Kdim + qB*4;
        sB[i] = qB*4*BPAD + colB;
    }

    int warp = tid >> 5, lane = tid & 31;
    int wm = warp >> 1, wn = warp & 1;
    int l4 = lane >> 2, lq = lane & 3;
    int am0 = wm*32;
    int bn0 = wn*64;

    float acc[2][8][4];
#pragma unroll
    for (int mt = 0; mt < 2; mt++)
#pragma unroll
        for (int nt = 0; nt < 8; nt++)
#pragma unroll
            for (int j = 0; j < 4; j++) acc[mt][nt][j] = 0.f;

    int nkt = Kdim >> 4;

    // prologue: stage 0
    cpa16(asb + sAb[0], pA[0]);
    cpa16(asb + sAb[1], pA[1]);
    asm volatile("cp.async.commit_group;" ::: "memory");
    float4 rb0 = *(const float4*)(pB[0]);
    float4 rb1 = *(const float4*)(pB[1]);
    {
        unsigned* B0 = &Bs[0][0][0];
        B0[sB[0]+0*BPAD]=__float_as_uint(rb0.x); B0[sB[0]+1*BPAD]=__float_as_uint(rb0.y);
        B0[sB[0]+2*BPAD]=__float_as_uint(rb0.z); B0[sB[0]+3*BPAD]=__float_as_uint(rb0.w);
        B0[sB[1]+0*BPAD]=__float_as_uint(rb1.x); B0[sB[1]+1*BPAD]=__float_as_uint(rb1.y);
        B0[sB[1]+2*BPAD]=__float_as_uint(rb1.z); B0[sB[1]+3*BPAD]=__float_as_uint(rb1.w);
    }
    asm volatile("cp.async.wait_group 0;" ::: "memory");
    __syncthreads();

    for (int kt = 0; kt < nkt; ++kt) {
        int cur = kt & 1, nxt = cur ^ 1;
        bool more = (kt + 1 < nkt);
        if (more) {
            int k0 = (kt + 1) * 16;
            cpa16(asb + (unsigned)nxt*ASTAGE + sAb[0], pA[0] + k0);
            cpa16(asb + (unsigned)nxt*ASTAGE + sAb[1], pA[1] + k0);
            asm volatile("cp.async.commit_group;" ::: "memory");
            rb0 = *(const float4*)(pB[0] + k0);
            rb1 = *(const float4*)(pB[1] + k0);
        }
        const unsigned* Ac = &As[cur][0][0];
        const unsigned* Bc = &Bs[cur][0][0];
#pragma unroll
        for (int kh = 0; kh < 16; kh += 8) {
            unsigned bf[8][2];
#pragma unroll
            for (int nt = 0; nt < 8; nt++) {
                bf[nt][0] = Bc[(kh + lq)*BPAD + bn0 + nt*8 + l4];
                bf[nt][1] = Bc[(kh + lq + 4)*BPAD + bn0 + nt*8 + l4];
            }
#pragma unroll
            for (int mt = 0; mt < 2; mt++) {
                int mr = am0 + mt*16 + l4;
                unsigned a0 = Ac[mr*APAD + kh + lq];
                unsigned a1 = Ac[(mr+8)*APAD + kh + lq];
                unsigned a2 = Ac[mr*APAD + kh + lq + 4];
                unsigned a3 = Ac[(mr+8)*APAD + kh + lq + 4];
#pragma unroll
                for (int nt = 0; nt < 8; nt++)
                    mma_tf32(acc[mt][nt], a0, a1, a2, a3, bf[nt][0], bf[nt][1]);
            }
        }
        __syncthreads();
        if (more) {
            unsigned* Bn = &Bs[nxt][0][0];
            Bn[sB[0]+0*BPAD]=__float_as_uint(rb0.x); Bn[sB[0]+1*BPAD]=__float_as_uint(rb0.y);
            Bn[sB[0]+2*BPAD]=__float_as_uint(rb0.z); Bn[sB[0]+3*BPAD]=__float_as_uint(rb0.w);
            Bn[sB[1]+0*BPAD]=__float_as_uint(rb1.x); Bn[sB[1]+1*BPAD]=__float_as_uint(rb1.y);
            Bn[sB[1]+2*BPAD]=__float_as_uint(rb1.z); Bn[sB[1]+3*BPAD]=__float_as_uint(rb1.w);
        }
        asm volatile("cp.async.wait_group 0;" ::: "memory");
        __syncthreads();
    }

    float* Cb = g_G + (size_t)dir*NROW*G4;
#pragma unroll
    for (int mt = 0; mt < 2; mt++) {
        int r = row0 + am0 + mt*16 + l4;
#pragma unroll
        for (int nt = 0; nt < 8; nt++) {
            int c = col0 + bn0 + nt*8 + 2*lq;
            float2 b1v = *(const float2*)(bi + c);
            float2 b2v = *(const float2*)(bh + c);
            float bx = b1v.x + b2v.x, by = b1v.y + b2v.y;
            float2 v0; v0.x = acc[mt][nt][0] + bx; v0.y = acc[mt][nt][1] + by;
            float2 v1; v1.x = acc[mt][nt][2] + bx; v1.y = acc[mt][nt][3] + by;
            *(float2*)(Cb + (size_t)r*G4 + c)     = v0;
            *(float2*)(Cb + (size_t)(r+8)*G4 + c) = v1;
        }
    }
}

// ---------------- fast activations ----------------
__device__ __forceinline__ float sigf(float x) {
    float e = __expf(-x);
    return __fdividef(1.f, 1.f + e);
}
__device__ __forceinline__ float tanhfast(float x) {
    float e = __expf(2.f*x);
    return 1.f - __fdividef(2.f, 1.f + e);
}

// ---------------- recurrent scan: shuffle reduction, one cluster barrier/step ----------------
// thread map: lane bit0 = k-half, bits1-2 = gate, tid>>3 = n (0..63). 512 threads.
// grid (64,2): 32 chunks x 2 ranks, 2 dirs.
__global__ __launch_bounds__(512, 1) __cluster_dims__(2, 1, 1)
void k_scan(const float* __restrict__ WhhF, const float* __restrict__ WhhB, int layer)
{
    __shared__ __align__(16) float hbuf[2*2*128];   // [phase][b][n global]  2KB

    int tid = threadIdx.x;
    int dir = blockIdx.y;
    unsigned rank; asm("mov.u32 %0, %%cluster_ctarank;" : "=r"(rank));
    unsigned peer = rank ^ 1u;
    int chunk = blockIdx.x >> 1;

    const float* Whh = dir ? WhhB : WhhF;
    float* Xout = (layer == 0) ? g_X1 : g_X2;
    const float* Gd = g_G + (size_t)dir*NROW*G4;

    int kh = tid & 1;              // k half: k in [kh*64, kh*64+64)
    int gt = (tid >> 1) & 3;       // gate 0..3 (i,f,g,o)
    int n  = tid >> 3;             // 0..63 local
    int ng = (int)rank*64 + n;     // global n
    int jrow = gt*128 + ng;        // W_hh row

    // weights: 64 consecutive k of row jrow, f32x2-packed, 16B loads
    unsigned long long wq[32];
    {
        const ulonglong2* wr = (const ulonglong2*)(Whh + (size_t)jrow*HH + kh*64);
#pragma unroll
        for (int q = 0; q < 16; q++) {
            ulonglong2 u = wr[q];
            wq[q*2]   = u.x;
            wq[q*2+1] = u.y;
        }
    }

    hbuf[tid] = 0.f;     // 512 floats = both phases
    __syncthreads();
    asm volatile("barrier.cluster.arrive.aligned;" ::: "memory");
    asm volatile("barrier.cluster.wait.aligned;"   ::: "memory");

    unsigned hb_r; { unsigned hl = (unsigned)__cvta_generic_to_shared(hbuf);
        asm("mapa.shared::cluster.u32 %0, %1, %2;" : "=r"(hb_r) : "r"(hl), "r"(peer)); }

    bool is_upd = ((tid & 7) == 0);   // kh==0 && gt==0 -> 64 update threads, each owns 2 b
    long long gstep = dir ? -(long long)(BB*G4) : (long long)(BB*G4);
    const float* gp0 = Gd + ((size_t)(dir ? TT-1 : 0)*BB + chunk*2 + 0)*G4 + ng;
    const float* gp1 = Gd + ((size_t)(dir ? TT-1 : 0)*BB + chunk*2 + 1)*G4 + ng;
    float gA[8];
    if (is_upd) {
        gA[0]=__ldg(gp0); gA[1]=__ldg(gp0+128); gA[2]=__ldg(gp0+256); gA[3]=__ldg(gp0+384);
        gA[4]=__ldg(gp1); gA[5]=__ldg(gp1+128); gA[6]=__ldg(gp1+256); gA[7]=__ldg(gp1+384);
    }
    float c0 = 0.f, c1 = .0f;
    size_t xbase0 = ((size_t)(chunk*2 + 0))*HD1 + dir*HH + ng;
    size_t xbase1 = ((size_t)(chunk*2 + 1))*HD1 + dir*HH + ng;

    for (int s = 0; s < TT; ++s) {
        // ---- matvec: 1 gate-col x 64 k x 2 b per thread ----
        const ulonglong2* H0 = (const ulonglong2*)(hbuf + (s & 1)*256 + kh*64);        // b0
        const ulonglong2* H1 = (const ulonglong2*)(hbuf + (s & 1)*256 + 128 + kh*64);  // b1
        unsigned long long a0 = 0ull, a1 = 0ull, a2 = 0ull, a3 = 0ull;
#pragma unroll
        for (int q = 0; q < 16; q++) {
            ulonglong2 x0 = H0[q];
            ulonglong2 x1 = H1[q];
            a0 = ff2(wq[q*2],   x0.x, a0);
            a1 = ff2(wq[q*2+1], x0.y, a1);
            a2 = ff2(wq[q*2],   x1.x, a2);
            a3 = ff2(wq[q*2+1], x1.y, a3);
        }
        float s0 = hsum2(a0) + hsum2(a1);   // partial (gate gt, n, b0, k-half kh)
        float s1 = hsum2(a2) + hsum2(a3);   // b1

        // ---- warp-shuffle reduction: combine k-halves, gather 4 gates ----
        s0 += __shfl_xor_sync(0xFFFFFFFFu, s0, 1);
        s1 += __shfl_xor_sync(0xFFFFFFFFu, s1, 1);
        float o0 = __shfl_xor_sync(0xFFFFFFFFu, s0, 2);   // partner gate (gt^1)
        float o1 = __shfl_xor_sync(0xFFFFFFFFu, s1, 2);
        float p0 = __shfl_xor_sync(0xFFFFFFFFu, s0, 4);   // gt^2's own gate
        float p1 = __shfl_xor_sync(0xFFFFFFFFu, o0, 4);   // gt^3's gate
        float q0 = __shfl_xor_sync(0xFFFFFFFFu, s1, 4);
        float q1 = __shfl_xor_sync(0xFFFFFFFFu, o1, 4);

        // ---- LSTM cell update (64 threads, 2 b each) ----
        if (is_upd) {
            // b0: i = gA[0]+s0, f = gA[1]+o0, g = gA[2]+p0, o = gA[3]+p1
            float iv0 = sigf(gA[0] + s0), fv0 = sigf(gA[1] + o0);
            float gv0 = tanhfast(gA[2] + p0), ov0 = sigf(gA[3] + p1);
            c0 = fv0*c0 + iv0*gv0;
            float h0n = ov0*tanhfast(c0);
            // b1
            float iv1 = sigf(gA[4] + s1), fv1 = sigf(gA[5] + o1);
            float gv1 = tanhfast(gA[6] + q0), ov1 = sigf(gA[7] + q1);
            c1 = fv1*c1 + iv1*gv1;
            float h1n = ov1*tanhfast(c1);

            int hoff = ((s+1) & 1)*256 + ng;
            hbuf[hoff]       = h0n;
            hbuf[hoff + 128] = h1n;
            asm volatile("st.shared::cluster.f32 [%0], %1;"
                         :: "r"(hb_r + (unsigned)hoff*4), "f"(h0n) : "memory");
            asm volatile("st.shared::cluster.f32 [%0], %1;"
                         :: "r"(hb_r + (unsigned)(hoff+128)*4), "f"(h1n) : "memory");
            int t = dir ? (TT-1-s) : s;
            Xout[(size_t)t*BB*HD1 + xbase0] = h0n;
            Xout[(size_t)t*BB*HD1 + xbase1] = h1n;
        }
        asm volatile("barrier.cluster.arrive.aligned;" ::: "memory");
        if (is_upd && (s + 1 < TT)) {       // prefetch next G under the barrier wait
            gp0 += gstep; gp1 += gstep;
            gA[0]=__ldg(gp0); gA[1]=__ldg(gp0+128); gA[2]=__ldg(gp0+256); gA[3]=__ldg(gp0+384);
            gA[4]=__ldg(gp1); gA[5]=__ldg(gp1+128); gA[6]=__ldg(gp1+256); gA[7]=__ldg(gp1+384);
        }
        asm volatile("barrier.cluster.wait.aligned;"   ::: "memory");
    }
}

// ---------------- post: BN1+Linear+tanh+BN2+output-proj fused -> g_HL ----------------
__global__ void __launch_bounds__(256) k_post()
{
    __shared__ float as[16][64];
    __shared__ float bs[16][64];
    __shared__ float Hs[64][65];
    __shared__ float wh[2*HD2];
    __shared__ float hbb[2];
    int tid = threadIdx.x;
    int row0 = blockIdx.x*64;
    if (tid < 128) wh[tid] = g_Wh2[tid];
    if (tid < 2)   hbb[tid] = g_hb[tid];

    int lr = tid >> 2, kq = (tid & 3)*4;
    const float* arow = g_X2 + (size_t)(row0 + lr)*HD1;
    const float* wrow = g_Wp + lr*HD1;
    int rowgrp = tid >> 4, colgrp = tid & 15;
    float acc[4][4];
#pragma unroll
    for (int i = 0; i < 4; i++)
#pragma unroll
        for (int j = 0; j < 4; j++) acc[i][j] = 0.f;

    for (int kt = 0; kt < 16; ++kt) {
        int k0 = kt*16;
        float4 av = *(const float4*)(arow + k0 + kq);
        float4 bv = *(const float4*)(wrow + k0 + kq);
        __syncthreads();
        as[kq+0][lr]=av.x; as[kq+1][lr]=av.y; as[kq+2][lr]=av.z; as[kq+3][lr]=av.w;
        bs[kq+0][lr]=bv.x; bs[kq+1][lr]=bv.y; bs[kq+2][lr]=bv.z; bs[kq+3][lr]=bv.w;
        __syncthreads();
#pragma unroll
        for (int kk = 0; kk < 16; ++kk) {
            float4 a4 = *(const float4*)&as[kk][rowgrp*4];
            float4 b4 = *(const float4*)&bs[kk][colgrp*4];
            acc[0][0]+=a4.x*b4.x; acc[0][1]+=a4.x*b4.y; acc[0][2]+=a4.x*b4.z; acc[0][3]+=a4.x*b4.w;
            acc[1][0]+=a4.y*b4.x; acc[1][1]+=a4.y*b4.y; acc[1][2]+=a4.y*b4.z; acc[1][3]+=a4.y*b4.w;
            acc[2][0]+=a4.z*b4.x; acc[2][1]+=a4.z*b4.y; acc[2][2]+=a4.z*b4.z; acc[2][3]+=a4.z*b4.w;
            acc[3][0]+=a4.w*b4.x; acc[3][1]+=a4.w*b4.y; acc[3][2]+=a4.w*b4.z; acc[3][3]+=a4.w*b4.w;
        }
    }
    __syncthreads();
#pragma unroll
    for (int i = 0; i < 4; i++)
#pragma unroll
        for (int j = 0; j < 4; j++) {
            int c = colgrp*4 + j;
            Hs[rowgrp*4 + i][c] = tanhf(acc[i][j] + g_bp[c]);
        }
    __syncthreads();
    if (tid < 128) {
        int r = tid >> 1, k = tid & 1;
        float a = hbb[k];
#pragma unroll
        for (int c = 0; c < HD2; c++) a += Hs[r][c]*wh[k*HD2 + c];
        g_HL[(size_t)(row0 + r)*2 + k] = a;
    }
}

// ---------------- context scan: 64 chains, cp.async double-buffered h ----------------
#define CCH 32
__global__ void __launch_bounds__(128) k_ctx(const float* __restrict__ outw, float* __restrict__ out)
{
    __shared__ __align__(16) float buf[2][CCH*BB*2];   // 32KB
    int tid = threadIdx.x;
    unsigned sb = (unsigned)__cvta_generic_to_shared(&buf[0][0]);
    const unsigned STAGE = CCH*BB*2*4;

    // prologue: chunk 0
    for (int i = tid*4; i < CCH*BB*2; i += 128*4)
        cpa16(sb + (unsigned)i*4, g_HL + i);
    asm volatile("cp.async.commit_group;" ::: "memory");
    asm volatile("cp.async.wait_group 0;" ::: "memory");
    __syncthreads();

    int b = tid;
    float W00=outw[0],  W01=outw[1],  W02=outw[2],  W03=outw[3];
    float W10=outw[68], W11=outw[69], W12=outw[70], W13=outw[71];
    float c0=0.f, c1=0.f, c2=0.f, c3=0.f;

    const int NCH = TT/CCH;
    for (int c = 0; c < NCH; ++c) {
        int cur = c & 1, nxt = cur ^ 1;
        if (c + 1 < NCH) {
            const float* src = g_HL + (size_t)(c+1)*CCH*BB*2;
            unsigned dst = sb + (unsigned)nxt*STAGE;
            for (int i = tid*4; i < CCH*BB*2; i += 128*4)
                cpa16(dst + (unsigned)i*4, src + i);
            asm volatile("cp.async.commit_group;" ::: "memory");
        }
        if (b < BB) {
            const float* pb = buf[cur];
            float* op = out + ((size_t)b*TT + c*CCH)*2;
#pragma unroll 4
            for (int j = 0; j < CCH; ++j) {
                float h0 = pb[(j*BB + b)*2 + 0];
                float h1 = pb[(j*BB + b)*2 + 1];
                float l0 = h0 + c0*W00 + c1*W01 + c2*W02 + c3*W03;
                float l1 = h1 + c0*W10 + c1*W11 + c2*W12 + c3*W13;
                float m  = fmaxf(l0, l1);
                float lse = m + __logf(__expf(l0 - m) + __expf(l1 - m));
                float o0 = l0 - lse, o1 = l1 - lse;
                op[j*2 + 0] = o0;
                op[j*2 + 1] = o1;
                c0 = c2; c1 = c3; c2 = o0; c3 = o1;
            }
        }
        asm volatile("cp.async.wait_group 0;" ::: "memory");
        __syncthreads();
    }
}

// ---------------- launch ----------------
extern "C" void kernel_launch(void* const* d_in, const int* in_sizes, int n_in,
                              void* d_out, int out_size)
{
    const float* x        = (const float*)d_in[0];
    const float* w_ih_l0  = (const float*)d_in[1];
    const float* w_hh_l0  = (const float*)d_in[2];
    const float* b_ih_l0  = (const float*)d_in[3];
    const float* b_hh_l0  = (const float*)d_in[4];
    const float* w_ih_l0r = (const float*)d_in[5];
    const float* w_hh_l0r = (const float*)d_in[6];
    const float* b_ih_l0r = (const float*)d_in[7];
    const float* b_hh_l0r = (const float*)d_in[8];
    const float* w_ih_l1  = (const float*)d_in[9];
    const float* w_hh_l1  = (const float*)d_in[10];
    const float* b_ih_l1  = (const float*)d_in[11];
    const float* b_hh_l1  = (const float*)d_in[12];
    const float* w_ih_l1r = (const float*)d_in[13];
    const float* w_hh_l1r = (const float*)d_in[14];
    const float* b_ih_l1r = (const float*)d_in[15];
    const float* b_hh_l1r = (const float*)d_in[16];
    const float* bn1_g    = (const float*)d_in[17];
    const float* bn1_b    = (const float*)d_in[18];
    const float* bn1_m    = (const float*)d_in[19];
    const float* bn1_v    = (const float*)d_in[20];
    const float* lin_w    = (const float*)d_in[21];
    const float* lin_b    = (const float*)d_in[22];
    const float* bn2_g    = (const float*)d_in[23];
    const float* bn2_b    = (const float*)d_in[24];
    const float* bn2_m    = (const float*)d_in[25];
    const float* bn2_v    = (const float*)d_in[26];
    const float* out_w    = (const float*)d_in[27];
    const float* out_b    = (const float*)d_in[28];

    k_prep<<<1, 256>>>(bn1_g, bn1_b, bn1_m, bn1_v, lin_w, lin_b,
                       bn2_g, bn2_b, bn2_m, bn2_v, out_w, out_b);

    dim3 gg(NROW/128, G4/128, 2);
    k_gemm<<<gg, 256>>>(x, w_ih_l0, b_ih_l0, b_hh_l0,
                           w_ih_l0r, b_ih_l0r, b_hh_l0r, DIN, 0);
    k_scan<<<dim3(64, 2), 512>>>(w_hh_l0, w_hh_l0r, 0);

    k_gemm<<<gg, 256>>>(x, w_ih_l1, b_ih_l1, b_hh_l1,
                           w_ih_l1r, b_ih_l1r, b_hh_l1r, HD1, 1);
    k_scan<<<dim3(64, 2), 512>>>(w_hh_l1, w_hh_l1r, 1);

    k_post<<<NROW/64, 256>>>();
    k_ctx<<<1, 128>>>(out_w, (float*)d_out);
}

// round 14
// speedup vs baseline: 2.2383x; 2.2383x over previous
#include <cuda_runtime.h>
#include <cuda_fp16.h>
#include <cstdint>

#define TT   1024
#define BB   64
#define DIN  400
#define HH   128
#define G4   512
#define HD1  256
#define HD2  64
#define NROW (TT*BB)

// ---------------- scratch (device globals; no runtime allocation) ----------------
__device__ float g_G  [(size_t)2*NROW*G4];   // gate preactivations, both dirs
__device__ float g_X1 [(size_t)NROW*HD1];    // layer0 output [t][b][256]
__device__ float g_X2 [(size_t)NROW*HD1];    // layer1 output [t][b][256]
__device__ float g_HL [(size_t)NROW*2];      // precomputed h-part of logits
__device__ float g_Wp [HD2*HD1];             // BN1-folded linear weight
__device__ float g_bp [HD2];                 // BN1-folded linear bias
__device__ float g_Wh2[2*HD2];               // BN2-folded output weight (h part)
__device__ float g_hb [2];                   // BN2-folded output bias

// ---------------- prep: fold BN1/BN2 into linear / output weights ----------------
__global__ void k_prep(const float* bn1g, const float* bn1b, const float* bn1m, const float* bn1v,
                       const float* linw, const float* linb,
                       const float* bn2g, const float* bn2b, const float* bn2m, const float* bn2v,
                       const float* outw, const float* outb) {
    __shared__ float s1[HD1], t1[HD1], s2[HD2], t2[HD2];
    int tid = threadIdx.x;
    if (tid < HD1) { float s = bn1g[tid]*rsqrtf(bn1v[tid]+1e-5f); s1[tid]=s; t1[tid]=bn1b[tid]-bn1m[tid]*s; }
    if (tid < HD2) { float s = bn2g[tid]*rsqrtf(bn2v[tid]+1e-5f); s2[tid]=s; t2[tid]=bn2b[tid]-bn2m[tid]*s; }
    __syncthreads();
    for (int i = tid; i < HD2*HD1; i += blockDim.x) g_Wp[i] = linw[i]*s1[i & (HD1-1)];
    if (tid < HD2) {
        float a = linb[tid];
        for (int j = 0; j < HD1; j++) a += t1[j]*linw[tid*HD1+j];
        g_bp[tid] = a;
    }
    if (tid < 2*HD2) { int k = tid>>6, c = tid&63; g_Wh2[tid] = outw[k*68+4+c]*s2[c]; }
    if (tid < 2) {
        float a = outb[tid];
        for (int c = 0; c < HD2; c++) a += t2[c]*outw[tid*68+4+c];
        g_hb[tid] = a;
    }
}

// ---------------- mma helpers ----------------
__device__ __forceinline__ void mma_tf32(float* c, unsigned a0, unsigned a1, unsigned a2, unsigned a3,
                                         unsigned b0, unsigned b1) {
    asm volatile("mma.sync.aligned.m16n8k8.row.col.f32.tf32.tf32.f32 "
                 "{%0,%1,%2,%3}, {%4,%5,%6,%7}, {%8,%9}, {%0,%1,%2,%3};"
                 : "+f"(c[0]), "+f"(c[1]), "+f"(c[2]), "+f"(c[3])
                 : "r"(a0), "r"(a1), "r"(a2), "r"(a3), "r"(b0), "r"(b1));
}
__device__ __forceinline__ void mma_f16(float* c, const unsigned* a, const unsigned* b) {
    asm volatile("mma.sync.aligned.m16n8k16.row.col.f32.f16.f16.f32 "
                 "{%0,%1,%2,%3}, {%4,%5,%6,%7}, {%8,%9}, {%0,%1,%2,%3};"
                 : "+f"(c[0]), "+f"(c[1]), "+f"(c[2]), "+f"(c[3])
                 : "r"(a[0]), "r"(a[1]), "r"(a[2]), "r"(a[3]), "r"(b[0]), "r"(b[1]));
}
__device__ __forceinline__ void cpa16(unsigned dst, const float* src) {
    asm volatile("cp.async.ca.shared.global [%0], [%1], 16;" :: "r"(dst), "l"(src) : "memory");
}
__device__ __forceinline__ unsigned pack2h(float lo, float hi) {
    __half2 h = __floats2half2_rn(lo, hi);
    return *(unsigned*)&h;
}

// ---------------- input-projection GEMM (tensor cores, tf32, cp.async) ----------------
#define APAD 20
#define BPAD 136
__global__ void __launch_bounds__(256) k_gemm(
    const float* __restrict__ x,
    const float* __restrict__ Wf, const float* __restrict__ bif, const float* __restrict__ bhf,
    const float* __restrict__ Wr, const float* __restrict__ bir, const float* __restrict__ bhr,
    int Kdim, int layer)
{
    __shared__ __align__(16) unsigned As[2][128][APAD];
    __shared__ __align__(16) unsigned Bs[2][16][BPAD];

    int tid  = threadIdx.x;
    int row0 = blockIdx.x*128, col0 = blockIdx.y*128;
    int dir  = blockIdx.z;
    const float* W  = dir ? Wr  : Wf;
    const float* bi = dir ? bir : bif;
    const float* bh = dir ? bhr : bhf;

    unsigned asb = (unsigned)__cvta_generic_to_shared(&As[0][0][0]);
    const unsigned ASTAGE = 128*APAD*4;

    const float* pA[2]; unsigned sAb[2];
    const float* pB[2]; int sB[2];
#pragma unroll
    for (int i = 0; i < 2; i++) {
        int t = tid + i*256;
        int rA = t >> 2, qA = t & 3;
        int r = row0 + rA;
        if (layer == 0) { int tt = r >> 6, b = r & 63; pA[i] = x + ((size_t)b*TT + tt)*DIN + qA*4; }
        else            { pA[i] = g_X1 + (size_t)r*HD1 + qA*4; }
        sAb[i] = (unsigned)(rA*APAD + qA*4)*4;
        int qB = t >> 7, colB = t & 127;
        pB[i] = W + (size_t)(col0 + colB)*Kdim + qB*4;
        sB[i] = qB*4*BPAD + colB;
    }

    int warp = tid >> 5, lane = tid & 31;
    int wm = warp >> 1, wn = warp & 1;
    int l4 = lane >> 2, lq = lane & 3;
    int am0 = wm*32;
    int bn0 = wn*64;

    float acc[2][8][4];
#pragma unroll
    for (int mt = 0; mt < 2; mt++)
#pragma unroll
        for (int nt = 0; nt < 8; nt++)
#pragma unroll
            for (int j = 0; j < 4; j++) acc[mt][nt][j] = 0.f;

    int nkt = Kdim >> 4;

    cpa16(asb + sAb[0], pA[0]);
    cpa16(asb + sAb[1], pA[1]);
    asm volatile("cp.async.commit_group;" ::: "memory");
    float4 rb0 = *(const float4*)(pB[0]);
    float4 rb1 = *(const float4*)(pB[1]);
    {
        unsigned* B0 = &Bs[0][0][0];
        B0[sB[0]+0*BPAD]=__float_as_uint(rb0.x); B0[sB[0]+1*BPAD]=__float_as_uint(rb0.y);
        B0[sB[0]+2*BPAD]=__float_as_uint(rb0.z); B0[sB[0]+3*BPAD]=__float_as_uint(rb0.w);
        B0[sB[1]+0*BPAD]=__float_as_uint(rb1.x); B0[sB[1]+1*BPAD]=__float_as_uint(rb1.y);
        B0[sB[1]+2*BPAD]=__float_as_uint(rb1.z); B0[sB[1]+3*BPAD]=__float_as_uint(rb1.w);
    }
    asm volatile("cp.async.wait_group 0;" ::: "memory");
    __syncthreads();

    for (int kt = 0; kt < nkt; ++kt) {
        int cur = kt & 1, nxt = cur ^ 1;
        bool more = (kt + 1 < nkt);
        if (more) {
            int k0 = (kt + 1) * 16;
            cpa16(asb + (unsigned)nxt*ASTAGE + sAb[0], pA[0] + k0);
            cpa16(asb + (unsigned)nxt*ASTAGE + sAb[1], pA[1] + k0);
            asm volatile("cp.async.commit_group;" ::: "memory");
            rb0 = *(const float4*)(pB[0] + k0);
            rb1 = *(const float4*)(pB[1] + k0);
        }
        const unsigned* Ac = &As[cur][0][0];
        const unsigned* Bc = &Bs[cur][0][0];
#pragma unroll
        for (int kh = 0; kh < 16; kh += 8) {
            unsigned bf[8][2];
#pragma unroll
            for (int nt = 0; nt < 8; nt++) {
                bf[nt][0] = Bc[(kh + lq)*BPAD + bn0 + nt*8 + l4];
                bf[nt][1] = Bc[(kh + lq + 4)*BPAD + bn0 + nt*8 + l4];
            }
#pragma unroll
            for (int mt = 0; mt < 2; mt++) {
                int mr = am0 + mt*16 + l4;
                unsigned a0 = Ac[mr*APAD + kh + lq];
                unsigned a1 = Ac[(mr+8)*APAD + kh + lq];
                unsigned a2 = Ac[mr*APAD + kh + lq + 4];
                unsigned a3 = Ac[(mr+8)*APAD + kh + lq + 4];
#pragma unroll
                for (int nt = 0; nt < 8; nt++)
                    mma_tf32(acc[mt][nt], a0, a1, a2, a3, bf[nt][0], bf[nt][1]);
            }
        }
        __syncthreads();
        if (more) {
            unsigned* Bn = &Bs[nxt][0][0];
            Bn[sB[0]+0*BPAD]=__float_as_uint(rb0.x); Bn[sB[0]+1*BPAD]=__float_as_uint(rb0.y);
            Bn[sB[0]+2*BPAD]=__float_as_uint(rb0.z); Bn[sB[0]+3*BPAD]=__float_as_uint(rb0.w);
            Bn[sB[1]+0*BPAD]=__float_as_uint(rb1.x); Bn[sB[1]+1*BPAD]=__float_as_uint(rb1.y);
            Bn[sB[1]+2*BPAD]=__float_as_uint(rb1.z); Bn[sB[1]+3*BPAD]=__float_as_uint(rb1.w);
        }
        asm volatile("cp.async.wait_group 0;" ::: "memory");
        __syncthreads();
    }

    float* Cb = g_G + (size_t)dir*NROW*G4;
#pragma unroll
    for (int mt = 0; mt < 2; mt++) {
        int r = row0 + am0 + mt*16 + l4;
#pragma unroll
        for (int nt = 0; nt < 8; nt++) {
            int c = col0 + bn0 + nt*8 + 2*lq;
            float2 b1v = *(const float2*)(bi + c);
            float2 b2v = *(const float2*)(bh + c);
            float bx = b1v.x + b2v.x, by = b1v.y + b2v.y;
            float2 v0; v0.x = acc[mt][nt][0] + bx; v0.y = acc[mt][nt][1] + by;
            float2 v1; v1.x = acc[mt][nt][2] + bx; v1.y = acc[mt][nt][3] + by;
            *(float2*)(Cb + (size_t)r*G4 + c)     = v0;
            *(float2*)(Cb + (size_t)(r+8)*G4 + c) = v1;
        }
    }
}

// ---------------- fast activations ----------------
__device__ __forceinline__ float sigf(float x) {
    float e = __expf(-x);
    return __fdividef(1.f, 1.f + e);
}
__device__ __forceinline__ float tanhfast(float x) {
    float e = __expf(2.f*x);
    return 1.f - __fdividef(2.f, 1.f + e);
}

// ---------------- recurrent scan: fp16 tensor-core matvec, single CTA, no cluster ----------------
// grid (32, 2): 32 batch-pair chunks x 2 dirs; 512 threads (16 warps).
// W_hh (512x128) lives entirely in registers as m16n8k16 A-fragments (64 regs/thread).
#define HPAD 136
__global__ __launch_bounds__(512, 1)
void k_scan(const float* __restrict__ WhhF, const float* __restrict__ WhhB, int layer)
{
    __shared__ __align__(16) float Gs[3][2][G4];      // gate preacts, triple buffer  12KB
    __shared__ __align__(16) float gbuf[G4*3];        // matvec result, pad stride 3   6KB
    __shared__ __align__(16) __half hT[2][2][HPAD];   // [phase][b][n] fp16 h        1088B

    int tid = threadIdx.x;
    int chunk = blockIdx.x;
    int dir = blockIdx.y;
    const float* Whh = dir ? WhhB : WhhF;
    float* Xout = (layer == 0) ? g_X1 : g_X2;
    const float* Gd = g_G + (size_t)dir*NROW*G4;

    int warp = tid >> 5, lane = tid & 31;
    int g = lane >> 2, qi = lane & 3;

    // ---- A-fragments: 2 Mtiles x 8 ktiles, fp16 ----
    unsigned AF[2][8][4];
#pragma unroll
    for (int mt = 0; mt < 2; mt++) {
        int m = 2*warp + mt;
        const float* w0 = Whh + (size_t)(16*m + g)*HH;
        const float* w1 = w0 + 8*HH;
#pragma unroll
        for (int kt = 0; kt < 8; kt++) {
            int kb = 16*kt + 2*qi;
            AF[mt][kt][0] = pack2h(w0[kb],   w0[kb+1]);
            AF[mt][kt][1] = pack2h(w1[kb],   w1[kb+1]);
            AF[mt][kt][2] = pack2h(w0[kb+8], w0[kb+9]);
            AF[mt][kt][3] = pack2h(w1[kb+8], w1[kb+9]);
        }
    }

    // zero h phase 0 (both batch rows)
    if (tid < 2*HPAD) ((__half*)hT)[tid] = __float2half_rn(0.f);

    // prologue: prefetch G for s = 0, 1
#pragma unroll
    for (int s = 0; s < 2; s++) {
        if (tid < 256) {
            int t = dir ? (TT-1-s) : s;
            int b = tid >> 7, w16 = tid & 127;
            const float* src = Gd + ((size_t)t*BB + chunk*2 + b)*G4 + w16*4;
            cpa16((unsigned)__cvta_generic_to_shared(&Gs[s][b][w16*4]), src);
        }
        asm volatile("cp.async.commit_group;" ::: "memory");
    }

    bool isu = (tid < 256);
    int n = tid & 127, bq = (tid >> 7) & 1;
    float creg = 0.f;
    size_t xbase = ((size_t)(chunk*2 + bq))*HD1 + dir*HH + n;
    int browoff = (g & 1) * HPAD;   // batch duplication for garbage mma cols

    __syncthreads();

    for (int s = 0; s < TT; ++s) {
        int ph = s & 1;
        // prefetch G for s+2
        if (s + 2 < TT && tid < 256) {
            int t2 = dir ? (TT-1-(s+2)) : (s+2);
            int b = tid >> 7, w16 = tid & 127;
            const float* src = Gd + ((size_t)t2*BB + chunk*2 + b)*G4 + w16*4;
            cpa16((unsigned)__cvta_generic_to_shared(&Gs[(s+2)%3][b][w16*4]), src);
        }
        asm volatile("cp.async.commit_group;" ::: "memory");

        // ---- B-fragments from fp16 h ----
        const __half* hp = &hT[ph][0][0];
        unsigned BF[8][2];
#pragma unroll
        for (int kt = 0; kt < 8; kt++) {
            BF[kt][0] = *(const unsigned*)(hp + browoff + 16*kt + 2*qi);
            BF[kt][1] = *(const unsigned*)(hp + browoff + 16*kt + 2*qi + 8);
        }

        // ---- mma: D[512,2] = W @ h ----
        float C0[4] = {0.f,0.f,0.f,0.f}, C1[4] = {0.f,0.f,0.f,0.f};
#pragma unroll
        for (int kt = 0; kt < 8; kt++) {
            mma_f16(C0, AF[0][kt], BF[kt]);
            mma_f16(C1, AF[1][kt], BF[kt]);
        }

        // ---- store valid cols (batch 0,1 -> qi==0 lanes); scalar stores (stride-3 layout) ----
        if (qi == 0) {
            int r0 = 16*(2*warp) + g;
            gbuf[3*r0 + 0]     = C0[0];
            gbuf[3*r0 + 1]     = C0[1];
            gbuf[3*(r0+8) + 0] = C0[2];
            gbuf[3*(r0+8) + 1] = C0[3];
            int r1 = r0 + 16;
            gbuf[3*r1 + 0]     = C1[0];
            gbuf[3*r1 + 1]     = C1[1];
            gbuf[3*(r1+8) + 0] = C1[2];
            gbuf[3*(r1+8) + 1] = C1[3];
        }
        __syncthreads();
        asm volatile("cp.async.wait_group 2;" ::: "memory");

        // ---- LSTM cell update: 256 threads, 1 (n,b) each ----
        if (isu) {
            const float* gsb = &Gs[s%3][bq][0];
            float w0 = gbuf[3*(      n) + bq] + gsb[      n];
            float w1 = gbuf[3*(128 + n) + bq] + gsb[128 + n];
            float w2 = gbuf[3*(256 + n) + bq] + gsb[256 + n];
            float w3 = gbuf[3*(384 + n) + bq] + gsb[384 + n];
            float iv = sigf(w0), fv = sigf(w1), gv = tanhfast(w2), ov = sigf(w3);
            creg = fv*creg + iv*gv;
            float h = ov*tanhfast(creg);
            hT[ph^1][bq][n] = __float2half_rn(h);
            int t = dir ? (TT-1-s) : s;
            Xout[(size_t)t*BB*HD1 + xbase] = h;
        }
        __syncthreads();
    }
}

// ---------------- post: BN1+Linear+tanh+BN2+output-proj fused -> g_HL ----------------
__global__ void __launch_bounds__(256) k_post()
{
    __shared__ float as[16][64];
    __shared__ float bs[16][64];
    __shared__ float Hs[64][65];
    __shared__ float wh[2*HD2];
    __shared__ float hbb[2];
    int tid = threadIdx.x;
    int row0 = blockIdx.x*64;
    if (tid < 128) wh[tid] = g_Wh2[tid];
    if (tid < 2)   hbb[tid] = g_hb[tid];

    int lr = tid >> 2, kq = (tid & 3)*4;
    const float* arow = g_X2 + (size_t)(row0 + lr)*HD1;
    const float* wrow = g_Wp + lr*HD1;
    int rowgrp = tid >> 4, colgrp = tid & 15;
    float acc[4][4];
#pragma unroll
    for (int i = 0; i < 4; i++)
#pragma unroll
        for (int j = 0; j < 4; j++) acc[i][j] = 0.f;

    for (int kt = 0; kt < 16; ++kt) {
        int k0 = kt*16;
        float4 av = *(const float4*)(arow + k0 + kq);
        float4 bv = *(const float4*)(wrow + k0 + kq);
        __syncthreads();
        as[kq+0][lr]=av.x; as[kq+1][lr]=av.y; as[kq+2][lr]=av.z; as[kq+3][lr]=av.w;
        bs[kq+0][lr]=bv.x; bs[kq+1][lr]=bv.y; bs[kq+2][lr]=bv.z; bs[kq+3][lr]=bv.w;
        __syncthreads();
#pragma unroll
        for (int kk = 0; kk < 16; ++kk) {
            float4 a4 = *(const float4*)&as[kk][rowgrp*4];
            float4 b4 = *(const float4*)&bs[kk][colgrp*4];
            acc[0][0]+=a4.x*b4.x; acc[0][1]+=a4.x*b4.y; acc[0][2]+=a4.x*b4.z; acc[0][3]+=a4.x*b4.w;
            acc[1][0]+=a4.y*b4.x; acc[1][1]+=a4.y*b4.y; acc[1][2]+=a4.y*b4.z; acc[1][3]+=a4.y*b4.w;
            acc[2][0]+=a4.z*b4.x; acc[2][1]+=a4.z*b4.y; acc[2][2]+=a4.z*b4.z; acc[2][3]+=a4.z*b4.w;
            acc[3][0]+=a4.w*b4.x; acc[3][1]+=a4.w*b4.y; acc[3][2]+=a4.w*b4.z; acc[3][3]+=a4.w*b4.w;
        }
    }
    __syncthreads();
#pragma unroll
    for (int i = 0; i < 4; i++)
#pragma unroll
        for (int j = 0; j < 4; j++) {
            int c = colgrp*4 + j;
            Hs[rowgrp*4 + i][c] = tanhf(acc[i][j] + g_bp[c]);
        }
    __syncthreads();
    if (tid < 128) {
        int r = tid >> 1, k = tid & 1;
        float a = hbb[k];
#pragma unroll
        for (int c = 0; c < HD2; c++) a += Hs[r][c]*wh[k*HD2 + c];
        g_HL[(size_t)(row0 + r)*2 + k] = a;
    }
}

// ---------------- context scan: 64 chains, cp.async double-buffered h ----------------
#define CCH 32
__global__ void __launch_bounds__(128) k_ctx(const float* __restrict__ outw, float* __restrict__ out)
{
    __shared__ __align__(16) float buf[2][CCH*BB*2];   // 32KB
    int tid = threadIdx.x;
    unsigned sb = (unsigned)__cvta_generic_to_shared(&buf[0][0]);
    const unsigned STAGE = CCH*BB*2*4;

    for (int i = tid*4; i < CCH*BB*2; i += 128*4)
        cpa16(sb + (unsigned)i*4, g_HL + i);
    asm volatile("cp.async.commit_group;" ::: "memory");
    asm volatile("cp.async.wait_group 0;" ::: "memory");
    __syncthreads();

    int b = tid;
    float W00=outw[0],  W01=outw[1],  W02=outw[2],  W03=outw[3];
    float W10=outw[68], W11=outw[69], W12=outw[70], W13=outw[71];
    float c0=0.f, c1=0.f, c2=0.f, c3=0.f;

    const int NCH = TT/CCH;
    for (int c = 0; c < NCH; ++c) {
        int cur = c & 1, nxt = cur ^ 1;
        if (c + 1 < NCH) {
            const float* src = g_HL + (size_t)(c+1)*CCH*BB*2;
            unsigned dst = sb + (unsigned)nxt*STAGE;
            for (int i = tid*4; i < CCH*BB*2; i += 128*4)
                cpa16(dst + (unsigned)i*4, src + i);
            asm volatile("cp.async.commit_group;" ::: "memory");
        }
        if (b < BB) {
            const float* pb = buf[cur];
            float* op = out + ((size_t)b*TT + c*CCH)*2;
#pragma unroll 4
            for (int j = 0; j < CCH; ++j) {
                float h0 = pb[(j*BB + b)*2 + 0];
                float h1 = pb[(j*BB + b)*2 + 1];
                float l0 = h0 + c0*W00 + c1*W01 + c2*W02 + c3*W03;
                float l1 = h1 + c0*W10 + c1*W11 + c2*W12 + c3*W13;
                float m  = fmaxf(l0, l1);
                float lse = m + __logf(__expf(l0 - m) + __expf(l1 - m));
                float o0 = l0 - lse, o1 = l1 - lse;
                op[j*2 + 0] = o0;
                op[j*2 + 1] = o1;
                c0 = c2; c1 = c3; c2 = o0; c3 = o1;
            }
        }
        asm volatile("cp.async.wait_group 0;" ::: "memory");
        __syncthreads();
    }
}

// ---------------- launch ----------------
extern "C" void kernel_launch(void* const* d_in, const int* in_sizes, int n_in,
                              void* d_out, int out_size)
{
    const float* x        = (const float*)d_in[0];
    const float* w_ih_l0  = (const float*)d_in[1];
    const float* w_hh_l0  = (const float*)d_in[2];
    const float* b_ih_l0  = (const float*)d_in[3];
    const float* b_hh_l0  = (const float*)d_in[4];
    const float* w_ih_l0r = (const float*)d_in[5];
    const float* w_hh_l0r = (const float*)d_in[6];
    const float* b_ih_l0r = (const float*)d_in[7];
    const float* b_hh_l0r = (const float*)d_in[8];
    const float* w_ih_l1  = (const float*)d_in[9];
    const float* w_hh_l1  = (const float*)d_in[10];
    const float* b_ih_l1  = (const float*)d_in[11];
    const float* b_hh_l1  = (const float*)d_in[12];
    const float* w_ih_l1r = (const float*)d_in[13];
    const float* w_hh_l1r = (const float*)d_in[14];
    const float* b_ih_l1r = (const float*)d_in[15];
    const float* b_hh_l1r = (const float*)d_in[16];
    const float* bn1_g    = (const float*)d_in[17];
    const float* bn1_b    = (const float*)d_in[18];
    const float* bn1_m    = (const float*)d_in[19];
    const float* bn1_v    = (const float*)d_in[20];
    const float* lin_w    = (const float*)d_in[21];
    const float* lin_b    = (const float*)d_in[22];
    const float* bn2_g    = (const float*)d_in[23];
    const float* bn2_b    = (const float*)d_in[24];
    const float* bn2_m    = (const float*)d_in[25];
    const float* bn2_v    = (const float*)d_in[26];
    const float* out_w    = (const float*)d_in[27];
    const float* out_b    = (const float*)d_in[28];

    k_prep<<<1, 256>>>(bn1_g, bn1_b, bn1_m, bn1_v, lin_w, lin_b,
                       bn2_g, bn2_b, bn2_m, bn2_v, out_w, out_b);

    dim3 gg(NROW/128, G4/128, 2);
    k_gemm<<<gg, 256>>>(x, w_ih_l0, b_ih_l0, b_hh_l0,
                           w_ih_l0r, b_ih_l0r, b_hh_l0r, DIN, 0);
    k_scan<<<dim3(32, 2), 512>>>(w_hh_l0, w_hh_l0r, 0);

    k_gemm<<<gg, 256>>>(x, w_ih_l1, b_ih_l1, b_hh_l1,
                           w_ih_l1r, b_ih_l1r, b_hh_l1r, HD1, 1);
    k_scan<<<dim3(32, 2), 512>>>(w_hh_l1, w_hh_l1r, 1);

    k_post<<<NROW/64, 256>>>();
    k_ctx<<<1, 128>>>(out_w, (float*)d_out);
}

// round 17
// speedup vs baseline: 2.5495x; 1.1390x over previous
#include <cuda_runtime.h>
#include <cuda_fp16.h>
#include <cstdint>

#define TT   1024
#define BB   64
#define DIN  400
#define HH   128
#define G4   512
#define HD1  256
#define HD2  64
#define NROW (TT*BB)

// ---------------- scratch (device globals; no runtime allocation) ----------------
__device__ float  g_G  [(size_t)2*NROW*G4];   // gate preactivations, both dirs
__device__ __half g_Xh [(size_t)BB*TT*DIN];   // fp16 copy of x
__device__ __half g_X1h[(size_t)NROW*HD1];    // layer0 output, fp16 [t][b][256]
__device__ float  g_X2 [(size_t)NROW*HD1];    // layer1 output [t][b][256]
__device__ __half g_Wh0 [512*DIN];            // fp16 weights
__device__ __half g_Wh0r[512*DIN];
__device__ __half g_Wh1 [512*HD1];
__device__ __half g_Wh1r[512*HD1];
__device__ float  g_HL [(size_t)NROW*2];      // precomputed h-part of logits
__device__ float  g_Wp [HD2*HD1];             // BN1-folded linear weight
__device__ float  g_bp [HD2];                 // BN1-folded linear bias
__device__ float  g_Wh2[2*HD2];               // BN2-folded output weight (h part)
__device__ float  g_hb [2];                   // BN2-folded output bias

// ---------------- prep: fold BN1/BN2 into linear / output weights ----------------
__global__ void k_prep(const float* bn1g, const float* bn1b, const float* bn1m, const float* bn1v,
                       const float* linw, const float* linb,
                       const float* bn2g, const float* bn2b, const float* bn2m, const float* bn2v,
                       const float* outw, const float* outb) {
    __shared__ float s1[HD1], t1[HD1], s2[HD2], t2[HD2];
    int tid = threadIdx.x;
    if (tid < HD1) { float s = bn1g[tid]*rsqrtf(bn1v[tid]+1e-5f); s1[tid]=s; t1[tid]=bn1b[tid]-bn1m[tid]*s; }
    if (tid < HD2) { float s = bn2g[tid]*rsqrtf(bn2v[tid]+1e-5f); s2[tid]=s; t2[tid]=bn2b[tid]-bn2m[tid]*s; }
    __syncthreads();
    for (int i = tid; i < HD2*HD1; i += blockDim.x) g_Wp[i] = linw[i]*s1[i & (HD1-1)];
    if (tid < HD2) {
        float a = linb[tid];
        for (int j = 0; j < HD1; j++) a += t1[j]*linw[tid*HD1+j];
        g_bp[tid] = a;
    }
    if (tid < 2*HD2) { int k = tid>>6, c = tid&63; g_Wh2[tid] = outw[k*68+4+c]*s2[c]; }
    if (tid < 2) {
        float a = outb[tid];
        for (int c = 0; c < HD2; c++) a += t2[c]*outw[tid*68+4+c];
        g_hb[tid] = a;
    }
}

// ---------------- fp32 -> fp16 conversion ----------------
__global__ void k_cvt(const float* __restrict__ s, int which, int n) {
    __half* d = (which == 0) ? g_Xh : (which == 1) ? g_Wh0 : (which == 2) ? g_Wh0r
              : (which == 3) ? g_Wh1 : g_Wh1r;
    for (int i = (blockIdx.x*blockDim.x + threadIdx.x)*4; i < n; i += gridDim.x*blockDim.x*4) {
        float4 v = *(const float4*)(s + i);
        *(__half2*)(d + i)     = __floats2half2_rn(v.x, v.y);
        *(__half2*)(d + i + 2) = __floats2half2_rn(v.z, v.w);
    }
}

// ---------------- mma helpers ----------------
__device__ __forceinline__ void mma_f16(float* c, const unsigned* a, const unsigned* b) {
    asm volatile("mma.sync.aligned.m16n8k16.row.col.f32.f16.f16.f32 "
                 "{%0,%1,%2,%3}, {%4,%5,%6,%7}, {%8,%9}, {%0,%1,%2,%3};"
                 : "+f"(c[0]), "+f"(c[1]), "+f"(c[2]), "+f"(c[3])
                 : "r"(a[0]), "r"(a[1]), "r"(a[2]), "r"(a[3]), "r"(b[0]), "r"(b[1]));
}
__device__ __forceinline__ void cpa16(unsigned dst, const void* src) {
    asm volatile("cp.async.ca.shared.global [%0], [%1], 16;" :: "r"(dst), "l"(src) : "memory");
}
__device__ __forceinline__ unsigned pack2h(float lo, float hi) {
    __half2 h = __floats2half2_rn(lo, hi);
    return *(unsigned*)&h;
}
__device__ __forceinline__ float tanha(float x) {
    float r; asm("tanh.approx.f32 %0, %1;" : "=f"(r) : "f"(x)); return r;
}
__device__ __forceinline__ float siga(float x) {
    return fmaf(0.5f, tanha(0.5f*x), 0.5f);
}

// ---------------- input-projection GEMM (fp16 tensor cores, cp.async) ----------------
// C[row, col] = sum_k A[row,k] * W[col,k] + bias. CTA tile 128x128, 8 warps, K-tile 16.
#define A2PAD 12
#define B2PAD 132
__global__ void __launch_bounds__(256) k_gemm(
    const float* __restrict__ bif, const float* __restrict__ bhf,
    const float* __restrict__ bir, const float* __restrict__ bhr,
    int Kdim, int layer)
{
    __shared__ __align__(16) unsigned As2[2][128][A2PAD];
    __shared__ __align__(16) unsigned Bs2[2][8][B2PAD];

    int tid  = threadIdx.x;
    int row0 = blockIdx.x*128, col0 = blockIdx.y*128;
    int dir  = blockIdx.z;
    const __half* Ain = layer ? g_X1h : g_Xh;
    const __half* W   = dir ? (layer ? g_Wh1r : g_Wh0r) : (layer ? g_Wh1 : g_Wh0);
    const float* bi = dir ? bir : bif;
    const float* bh = dir ? bhr : bhf;

    unsigned asb = (unsigned)__cvta_generic_to_shared(&As2[0][0][0]);
    const unsigned ASTAGE = 128*A2PAD*4;

    // loader roles
    int rA = tid >> 1, qA = tid & 1;
    const __half* pA;
    {
        int r = row0 + rA;
        if (layer == 0) { int tt = r >> 6, b = r & 63; pA = g_Xh + ((size_t)b*TT + tt)*DIN + qA*8; }
        else            { pA = g_X1h + (size_t)r*HD1 + qA*8; }
    }
    unsigned sAb = (unsigned)(rA*A2PAD + qA*4)*4;
    int colB = tid & 127, qB = tid >> 7;
    const __half* pB = W + (size_t)(col0 + colB)*Kdim + qB*8;

    // mma roles
    int warp = tid >> 5, lane = tid & 31;
    int wm = warp >> 1, wn = warp & 1;
    int g = lane >> 2, qi = lane & 3;
    int am0 = wm*32;
    int bn0 = wn*64;

    float acc[2][8][4];
#pragma unroll
    for (int mt = 0; mt < 2; mt++)
#pragma unroll
        for (int nt = 0; nt < 8; nt++)
#pragma unroll
            for (int j = 0; j < 4; j++) acc[mt][nt][j] = 0.f;

    int nkt = Kdim >> 4;

    // prologue: stage 0
    cpa16(asb + sAb, pA);
    asm volatile("cp.async.commit_group;" ::: "memory");
    uint4 rb = *(const uint4*)pB;
    {
        Bs2[0][qB*4+0][colB] = rb.x;
        Bs2[0][qB*4+1][colB] = rb.y;
        Bs2[0][qB*4+2][colB] = rb.z;
        Bs2[0][qB*4+3][colB] = rb.w;
    }
    asm volatile("cp.async.wait_group 0;" ::: "memory");
    __syncthreads();

    for (int kt = 0; kt < nkt; ++kt) {
        int cur = kt & 1, nxt = cur ^ 1;
        bool more = (kt + 1 < nkt);
        if (more) {
            int k0 = (kt + 1) * 16;
            cpa16(asb + (unsigned)nxt*ASTAGE + sAb, pA + k0);
            asm volatile("cp.async.commit_group;" ::: "memory");
            rb = *(const uint4*)(pB + k0);
        }
        const unsigned (*Ac)[A2PAD] = As2[cur];
        const unsigned (*Bc)[B2PAD] = Bs2[cur];
        unsigned bf[8][2];
#pragma unroll
        for (int nt = 0; nt < 8; nt++) {
            int c = bn0 + nt*8 + g;
            bf[nt][0] = Bc[qi][c];
            bf[nt][1] = Bc[qi+4][c];
        }
#pragma unroll
        for (int mt = 0; mt < 2; mt++) {
            int mr = am0 + mt*16 + g;
            unsigned a[4];
            a[0] = Ac[mr][qi];
            a[1] = Ac[mr+8][qi];
            a[2] = Ac[mr][qi+4];
            a[3] = Ac[mr+8][qi+4];
#pragma unroll
            for (int nt = 0; nt < 8; nt++)
                mma_f16(acc[mt][nt], a, bf[nt]);
        }
        __syncthreads();
        if (more) {
            Bs2[nxt][qB*4+0][colB] = rb.x;
            Bs2[nxt][qB*4+1][colB] = rb.y;
            Bs2[nxt][qB*4+2][colB] = rb.z;
            Bs2[nxt][qB*4+3][colB] = rb.w;
        }
        asm volatile("cp.async.wait_group 0;" ::: "memory");
        __syncthreads();
    }

    float* Cb = g_G + (size_t)dir*NROW*G4;
#pragma unroll
    for (int mt = 0; mt < 2; mt++) {
        int r = row0 + am0 + mt*16 + g;
#pragma unroll
        for (int nt = 0; nt < 8; nt++) {
            int c = col0 + bn0 + nt*8 + 2*qi;
            float2 b1v = *(const float2*)(bi + c);
            float2 b2v = *(const float2*)(bh + c);
            float bx = b1v.x + b2v.x, by = b1v.y + b2v.y;
            float2 v0; v0.x = acc[mt][nt][0] + bx; v0.y = acc[mt][nt][1] + by;
            float2 v1; v1.x = acc[mt][nt][2] + bx; v1.y = acc[mt][nt][3] + by;
            *(float2*)(Cb + (size_t)r*G4 + c)     = v0;
            *(float2*)(Cb + (size_t)(r+8)*G4 + c) = v1;
        }
    }
}

// ---------------- recurrent scan: fp16 tensor-core matvec, single CTA ----------------
// grid (32, 2): 32 batch-pair chunks x 2 dirs; 512 threads (16 warps).
#define HPAD 136
__global__ __launch_bounds__(512, 1)
void k_scan(const float* __restrict__ WhhF, const float* __restrict__ WhhB, int layer)
{
    __shared__ __align__(16) float Gs[3][2][G4];      // gate preacts, triple buffer  12KB
    __shared__ __align__(16) float gbuf[G4*3];        // matvec result, pad stride 3   6KB
    __shared__ __align__(16) __half hT[2][2][HPAD];   // [phase][b][n] fp16 h

    int tid = threadIdx.x;
    int chunk = blockIdx.x;
    int dir = blockIdx.y;
    const float* Whh = dir ? WhhB : WhhF;
    const float* Gd = g_G + (size_t)dir*NROW*G4;

    int warp = tid >> 5, lane = tid & 31;
    int g = lane >> 2, qi = lane & 3;

    // ---- A-fragments: 2 Mtiles x 8 ktiles, fp16 ----
    unsigned AF[2][8][4];
#pragma unroll
    for (int mt = 0; mt < 2; mt++) {
        int m = 2*warp + mt;
        const float* w0 = Whh + (size_t)(16*m + g)*HH;
        const float* w1 = w0 + 8*HH;
#pragma unroll
        for (int kt = 0; kt < 8; kt++) {
            int kb = 16*kt + 2*qi;
            AF[mt][kt][0] = pack2h(w0[kb],   w0[kb+1]);
            AF[mt][kt][1] = pack2h(w1[kb],   w1[kb+1]);
            AF[mt][kt][2] = pack2h(w0[kb+8], w0[kb+9]);
            AF[mt][kt][3] = pack2h(w1[kb+8], w1[kb+9]);
        }
    }

    if (tid < 2*HPAD) ((__half*)hT)[tid] = __float2half_rn(0.f);

    // prologue: prefetch G for s = 0, 1
#pragma unroll
    for (int s = 0; s < 2; s++) {
        if (tid < 256) {
            int t = dir ? (TT-1-s) : s;
            int b = tid >> 7, w16 = tid & 127;
            const float* src = Gd + ((size_t)t*BB + chunk*2 + b)*G4 + w16*4;
            cpa16((unsigned)__cvta_generic_to_shared(&Gs[s][b][w16*4]), src);
        }
        asm volatile("cp.async.commit_group;" ::: "memory");
    }

    bool isu = (tid < 256);
    int n = tid & 127, bq = (tid >> 7) & 1;
    float creg = 0.f;
    size_t xbase = ((size_t)(chunk*2 + bq))*HD1 + dir*HH + n;
    int browoff = (g & 1) * HPAD;

    __syncthreads();

    for (int s = 0; s < TT; ++s) {
        int ph = s & 1;
        if (s + 2 < TT && tid < 256) {
            int t2 = dir ? (TT-1-(s+2)) : (s+2);
            int b = tid >> 7, w16 = tid & 127;
            const float* src = Gd + ((size_t)t2*BB + chunk*2 + b)*G4 + w16*4;
            cpa16((unsigned)__cvta_generic_to_shared(&Gs[(s+2)%3][b][w16*4]), src);
        }
        asm volatile("cp.async.commit_group;" ::: "memory");

        // ---- B-fragments from fp16 h ----
        const __half* hp = &hT[ph][0][0];
        unsigned BF[8][2];
#pragma unroll
        for (int kt = 0; kt < 8; kt++) {
            BF[kt][0] = *(const unsigned*)(hp + browoff + 16*kt + 2*qi);
            BF[kt][1] = *(const unsigned*)(hp + browoff + 16*kt + 2*qi + 8);
        }

        // ---- mma: split 8-deep chains into 2x4 for latency ----
        float C0a[4] = {0.f,0.f,0.f,0.f}, C0b[4] = {0.f,0.f,0.f,0.f};
        float C1a[4] = {0.f,0.f,0.f,0.f}, C1b[4] = {0.f,0.f,0.f,0.f};
#pragma unroll
        for (int kt = 0; kt < 4; kt++) {
            mma_f16(C0a, AF[0][kt],   BF[kt]);
            mma_f16(C0b, AF[0][kt+4], BF[kt+4]);
            mma_f16(C1a, AF[1][kt],   BF[kt]);
            mma_f16(C1b, AF[1][kt+4], BF[kt+4]);
        }

        if (qi == 0) {
            int r0 = 16*(2*warp) + g;
            gbuf[3*r0 + 0]     = C0a[0] + C0b[0];
            gbuf[3*r0 + 1]     = C0a[1] + C0b[1];
            gbuf[3*(r0+8) + 0] = C0a[2] + C0b[2];
            gbuf[3*(r0+8) + 1] = C0a[3] + C0b[3];
            int r1 = r0 + 16;
            gbuf[3*r1 + 0]     = C1a[0] + C1b[0];
            gbuf[3*r1 + 1]     = C1a[1] + C1b[1];
            gbuf[3*(r1+8) + 0] = C1a[2] + C1b[2];
            gbuf[3*(r1+8) + 1] = C1a[3] + C1b[3];
        }
        __syncthreads();
        asm volatile("cp.async.wait_group 2;" ::: "memory");

        // ---- LSTM cell update: 256 threads, 1 (n,b) each ----
        if (isu) {
            const float* gsb = &Gs[s%3][bq][0];
            float w0 = gbuf[3*(      n) + bq] + gsb[      n];
            float w1 = gbuf[3*(128 + n) + bq] + gsb[128 + n];
            float w2 = gbuf[3*(256 + n) + bq] + gsb[256 + n];
            float w3 = gbuf[3*(384 + n) + bq] + gsb[384 + n];
            float iv = siga(w0), fv = siga(w1), gv = tanha(w2), ov = siga(w3);
            creg = fv*creg + iv*gv;
            float h = ov*tanha(creg);
            __half hh = __float2half_rn(h);
            hT[ph^1][bq][n] = hh;
            int t = dir ? (TT-1-s) : s;
            if (layer == 0) g_X1h[(size_t)t*BB*HD1 + xbase] = hh;
            else            g_X2 [(size_t)t*BB*HD1 + xbase] = h;
        }
        __syncthreads();
    }
}

// ---------------- post: BN1+Linear+tanh+BN2+output-proj fused -> g_HL ----------------
__global__ void __launch_bounds__(256) k_post()
{
    __shared__ float as[16][64];
    __shared__ float bs[16][64];
    __shared__ float Hs[64][65];
    __shared__ float wh[2*HD2];
    __shared__ float hbb[2];
    int tid = threadIdx.x;
    int row0 = blockIdx.x*64;
    if (tid < 128) wh[tid] = g_Wh2[tid];
    if (tid < 2)   hbb[tid] = g_hb[tid];

    int lr = tid >> 2, kq = (tid & 3)*4;
    const float* arow = g_X2 + (size_t)(row0 + lr)*HD1;
    const float* wrow = g_Wp + lr*HD1;
    int rowgrp = tid >> 4, colgrp = tid & 15;
    float acc[4][4];
#pragma unroll
    for (int i = 0; i < 4; i++)
#pragma unroll
        for (int j = 0; j < 4; j++) acc[i][j] = 0.f;

    for (int kt = 0; kt < 16; ++kt) {
        int k0 = kt*16;
        float4 av = *(const float4*)(arow + k0 + kq);
        float4 bv = *(const float4*)(wrow + k0 + kq);
        __syncthreads();
        as[kq+0][lr]=av.x; as[kq+1][lr]=av.y; as[kq+2][lr]=av.z; as[kq+3][lr]=av.w;
        bs[kq+0][lr]=bv.x; bs[kq+1][lr]=bv.y; bs[kq+2][lr]=bv.z; bs[kq+3][lr]=bv.w;
        __syncthreads();
#pragma unroll
        for (int kk = 0; kk < 16; ++kk) {
            float4 a4 = *(const float4*)&as[kk][rowgrp*4];
            float4 b4 = *(const float4*)&bs[kk][colgrp*4];
            acc[0][0]+=a4.x*b4.x; acc[0][1]+=a4.x*b4.y; acc[0][2]+=a4.x*b4.z; acc[0][3]+=a4.x*b4.w;
            acc[1][0]+=a4.y*b4.x; acc[1][1]+=a4.y*b4.y; acc[1][2]+=a4.y*b4.z; acc[1][3]+=a4.y*b4.w;
            acc[2][0]+=a4.z*b4.x; acc[2][1]+=a4.z*b4.y; acc[2][2]+=a4.z*b4.z; acc[2][3]+=a4.z*b4.w;
            acc[3][0]+=a4.w*b4.x; acc[3][1]+=a4.w*b4.y; acc[3][2]+=a4.w*b4.z; acc[3][3]+=a4.w*b4.w;
        }
    }
    __syncthreads();
#pragma unroll
    for (int i = 0; i < 4; i++)
#pragma unroll
        for (int j = 0; j < 4; j++) {
            int c = colgrp*4 + j;
            Hs[rowgrp*4 + i][c] = tanhf(acc[i][j] + g_bp[c]);
        }
    __syncthreads();
    if (tid < 128) {
        int r = tid >> 1, k = tid & 1;
        float a = hbb[k];
#pragma unroll
        for (int c = 0; c < HD2; c++) a += Hs[r][c]*wh[k*HD2 + c];
        g_HL[(size_t)(row0 + r)*2 + k] = a;
    }
}

// ---------------- context scan: 64 chains, cp.async double-buffered h ----------------
#define CCH 32
__global__ void __launch_bounds__(128) k_ctx(const float* __restrict__ outw, float* __restrict__ out)
{
    __shared__ __align__(16) float buf[2][CCH*BB*2];   // 32KB
    int tid = threadIdx.x;
    unsigned sb = (unsigned)__cvta_generic_to_shared(&buf[0][0]);
    const unsigned STAGE = CCH*BB*2*4;

    for (int i = tid*4; i < CCH*BB*2; i += 128*4)
        cpa16(sb + (unsigned)i*4, g_HL + i);
    asm volatile("cp.async.commit_group;" ::: "memory");
    asm volatile("cp.async.wait_group 0;" ::: "memory");
    __syncthreads();

    int b = tid;
    float W00=outw[0],  W01=outw[1],  W02=outw[2],  W03=outw[3];
    float W10=outw[68], W11=outw[69], W12=outw[70], W13=outw[71];
    float c0=0.f, c1=0.f, c2=0.f, c3=0.f;

    const int NCH = TT/CCH;
    for (int c = 0; c < NCH; ++c) {
        int cur = c & 1, nxt = cur ^ 1;
        if (c + 1 < NCH) {
            const float* src = g_HL + (size_t)(c+1)*CCH*BB*2;
            unsigned dst = sb + (unsigned)nxt*STAGE;
            for (int i = tid*4; i < CCH*BB*2; i += 128*4)
                cpa16(dst + (unsigned)i*4, src + i);
            asm volatile("cp.async.commit_group;" ::: "memory");
        }
        if (b < BB) {
            const float* pb = buf[cur];
            float* op = out + ((size_t)b*TT + c*CCH)*2;
#pragma unroll 4
            for (int j = 0; j < CCH; ++j) {
                float h0 = pb[(j*BB + b)*2 + 0];
                float h1 = pb[(j*BB + b)*2 + 1];
                float l0 = h0 + c0*W00 + c1*W01 + c2*W02 + c3*W03;
                float l1 = h1 + c0*W10 + c1*W11 + c2*W12 + c3*W13;
                float m  = fmaxf(l0, l1);
                float lse = m + __logf(__expf(l0 - m) + __expf(l1 - m));
                float o0 = l0 - lse, o1 = l1 - lse;
                op[j*2 + 0] = o0;
                op[j*2 + 1] = o1;
                c0 = c2; c1 = c3; c2 = o0; c3 = o1;
            }
        }
        asm volatile("cp.async.wait_group 0;" ::: "memory");
        __syncthreads();
    }
}

// ---------------- launch ----------------
extern "C" void kernel_launch(void* const* d_in, const int* in_sizes, int n_in,
                              void* d_out, int out_size)
{
    const float* x        = (const float*)d_in[0];
    const float* w_ih_l0  = (const float*)d_in[1];
    const float* w_hh_l0  = (const float*)d_in[2];
    const float* b_ih_l0  = (const float*)d_in[3];
    const float* b_hh_l0  = (const float*)d_in[4];
    const float* w_ih_l0r = (const float*)d_in[5];
    const float* w_hh_l0r = (const float*)d_in[6];
    const float* b_ih_l0r = (const float*)d_in[7];
    const float* b_hh_l0r = (const float*)d_in[8];
    const float* w_ih_l1  = (const float*)d_in[9];
    const float* w_hh_l1  = (const float*)d_in[10];
    const float* b_ih_l1  = (const float*)d_in[11];
    const float* b_hh_l1  = (const float*)d_in[12];
    const float* w_ih_l1r = (const float*)d_in[13];
    const float* w_hh_l1r = (const float*)d_in[14];
    const float* b_ih_l1r = (const float*)d_in[15];
    const float* b_hh_l1r = (const float*)d_in[16];
    const float* bn1_g    = (const float*)d_in[17];
    const float* bn1_b    = (const float*)d_in[18];
    const float* bn1_m    = (const float*)d_in[19];
    const float* bn1_v    = (const float*)d_in[20];
    const float* lin_w    = (const float*)d_in[21];
    const float* lin_b    = (const float*)d_in[22];
    const float* bn2_g    = (const float*)d_in[23];
    const float* bn2_b    = (const float*)d_in[24];
    const float* bn2_m    = (const float*)d_in[25];
    const float* bn2_v    = (const float*)d_in[26];
    const float* out_w    = (const float*)d_in[27];
    const float* out_b    = (const float*)d_in[28];

    k_prep<<<1, 256>>>(bn1_g, bn1_b, bn1_m, bn1_v, lin_w, lin_b,
                       bn2_g, bn2_b, bn2_m, bn2_v, out_w, out_b);

    // fp16 conversions
    k_cvt<<<6400, 256>>>(x,        0, BB*TT*DIN);
    k_cvt<<<200,  256>>>(w_ih_l0,  1, 512*DIN);
    k_cvt<<<200,  256>>>(w_ih_l0r, 2, 512*DIN);
    k_cvt<<<128,  256>>>(w_ih_l1,  3, 512*HD1);
    k_cvt<<<128,  256>>>(w_ih_l1r, 4, 512*HD1);

    dim3 gg(NROW/128, G4/128, 2);
    k_gemm<<<gg, 256>>>(b_ih_l0, b_hh_l0, b_ih_l0r, b_hh_l0r, DIN, 0);
    k_scan<<<dim3(32, 2), 512>>>(w_hh_l0, w_hh_l0r, 0);

    k_gemm<<<gg, 256>>>(b_ih_l1, b_hh_l1, b_ih_l1r, b_hh_l1r, HD1, 1);
    k_scan<<<dim3(32, 2), 512>>>(w_hh_l1, w_hh_l1r, 1);

    k_post<<<NROW/64, 256>>>();
    k_ctx<<<1, 128>>>(out_w, (float*)d_out);
}